// round 14
// baseline (speedup 1.0000x reference)
#include <cuda_runtime.h>
#include <cuda_bf16.h>
#include <cuda_fp16.h>
#include <cstdint>
#include <math.h>

// ---------------------------------------------------------------------------
// Res_GCN: 2-layer GCN + heads, bf16-split tensor-core GEMMs (mma.sync).
// Features h0, h stored fp16 (256 B/row). GEMM loads A once per row-tile,
// compile-time NSEG column-segment loop. out1 head fused into GEMM2 epilogue.
//   h   = relu(Agg(x@W1) + b1)
//   agg = Agg(h)
//   feat_label = agg@W2 + b2 ; out_pca = agg@((W2+W2u)Wpca^T)+b' ;
//   out_bce = agg@(W2u Wbce^T)+b'' ; out1 = ((flab/||.||)@Wh1^T + bh1)/0.1
// ---------------------------------------------------------------------------

#define MAXN 50000
#define MAXE 800000
#define H 128

__device__ __half g_h0f[MAXN * H];            // x @ W1 (fp16)
__device__ __half g_hf[MAXN * H];             // relu(Agg(h0)+b1) (fp16)
__device__ __nv_bfloat16 g_aggh[MAXN * H];    // Agg(h) hi
__device__ __nv_bfloat16 g_aggl[MAXN * H];    // Agg(h) lo
__device__ __nv_bfloat16 g_Wbh[H * 384];      // folded layer-2 weights hi (K-major)
__device__ __nv_bfloat16 g_Wbl[H * 384];      // folded layer-2 weights lo
__device__ float g_bbig[384];
__device__ float g_dinv[MAXN];
__device__ int   g_deg[MAXN];
__device__ int   g_rowptr[MAXN + 1];
__device__ int   g_cursor[MAXN];
__device__ int   g_col[MAXE];
__device__ int   g_bsum[64];

// ------------------------- helpers -----------------------------------------

__device__ __forceinline__ void split_bf16(float a, unsigned short& hi, unsigned short& lo) {
    __nv_bfloat16 h = __float2bfloat16_rn(a);
    float r = a - __bfloat162float(h);
    __nv_bfloat16 l = __float2bfloat16_rn(r);
    hi = *(unsigned short*)&h;
    lo = *(unsigned short*)&l;
}

__device__ __forceinline__ float4 dec4(const __half* __restrict__ row, int lane) {
    uint2 v = *(const uint2*)(row + lane * 4);       // 8 B: 4 fp16
    float2 f01 = __half22float2(*(__half2*)&v.x);
    float2 f23 = __half22float2(*(__half2*)&v.y);
    return make_float4(f01.x, f01.y, f23.x, f23.y);
}

__device__ __forceinline__ void ldsm4(uint32_t& r0, uint32_t& r1, uint32_t& r2, uint32_t& r3,
                                      uint32_t addr) {
    asm volatile("ldmatrix.sync.aligned.m8n8.x4.shared.b16 {%0,%1,%2,%3}, [%4];\n"
                 : "=r"(r0), "=r"(r1), "=r"(r2), "=r"(r3) : "r"(addr));
}

__device__ __forceinline__ void ldsm4t(uint32_t& r0, uint32_t& r1, uint32_t& r2, uint32_t& r3,
                                       uint32_t addr) {
    asm volatile("ldmatrix.sync.aligned.m8n8.x4.trans.shared.b16 {%0,%1,%2,%3}, [%4];\n"
                 : "=r"(r0), "=r"(r1), "=r"(r2), "=r"(r3) : "r"(addr));
}

__device__ __forceinline__ void mma_bf16(float* d, const uint32_t* a, const uint32_t* b) {
    asm volatile("mma.sync.aligned.m16n8k16.row.col.f32.bf16.bf16.f32 "
                 "{%0,%1,%2,%3}, {%4,%5,%6,%7}, {%8,%9}, {%0,%1,%2,%3};\n"
                 : "+f"(d[0]), "+f"(d[1]), "+f"(d[2]), "+f"(d[3])
                 : "r"(a[0]), "r"(a[1]), "r"(a[2]), "r"(a[3]), "r"(b[0]), "r"(b[1]));
}

// ------------------------- graph prep --------------------------------------

__global__ void zero_deg_kernel(int n) {
    int i = blockIdx.x * blockDim.x + threadIdx.x;
    if (i < n) g_deg[i] = 0;
}

__global__ void hist_kernel(const int* __restrict__ dst, int e) {
    int i = (blockIdx.x * blockDim.x + threadIdx.x) * 4;
    if (i + 3 < e) {
        int4 d = *(const int4*)&dst[i];
        atomicAdd(&g_deg[d.x], 1);
        atomicAdd(&g_deg[d.y], 1);
        atomicAdd(&g_deg[d.z], 1);
        atomicAdd(&g_deg[d.w], 1);
    } else {
        for (int j = i; j < e; j++) atomicAdd(&g_deg[dst[j]], 1);
    }
}

// block-local scan: 256 threads x 4 items = 1024 per block; also emits dinv
__global__ void blockscan_kernel(int n) {
    __shared__ int s[256];
    int t = threadIdx.x;
    int base = blockIdx.x * 1024 + t * 4;
    int v0 = (base + 0 < n) ? g_deg[base + 0] : 0;
    int v1 = (base + 1 < n) ? g_deg[base + 1] : 0;
    int v2 = (base + 2 < n) ? g_deg[base + 2] : 0;
    int v3 = (base + 3 < n) ? g_deg[base + 3] : 0;
    if (base + 0 < n) g_dinv[base + 0] = rsqrtf((float)(v0 + 1));
    if (base + 1 < n) g_dinv[base + 1] = rsqrtf((float)(v1 + 1));
    if (base + 2 < n) g_dinv[base + 2] = rsqrtf((float)(v2 + 1));
    if (base + 3 < n) g_dinv[base + 3] = rsqrtf((float)(v3 + 1));
    int sum = v0 + v1 + v2 + v3;
    s[t] = sum;
    __syncthreads();
    for (int off = 1; off < 256; off <<= 1) {
        int tv = (t >= off) ? s[t - off] : 0;
        __syncthreads();
        s[t] += tv;
        __syncthreads();
    }
    int run = s[t] - sum;
    if (base + 0 < n) { g_rowptr[base + 0] = run; } run += v0;
    if (base + 1 < n) { g_rowptr[base + 1] = run; } run += v1;
    if (base + 2 < n) { g_rowptr[base + 2] = run; } run += v2;
    if (base + 3 < n) { g_rowptr[base + 3] = run; }
    if (t == 255) g_bsum[blockIdx.x] = s[255];
}

// addoff: one block per 1024 nodes (same tiling as blockscan); thread 0
// serially prefix-sums the <=64 block sums (cached), removing bsum_scan.
__global__ void addoff_kernel(int n, int e) {
    __shared__ int off_s;
    if (threadIdx.x == 0) {
        int o = 0;
        for (int b = 0; b < (int)blockIdx.x; b++) o += g_bsum[b];
        off_s = o;
    }
    __syncthreads();
    int off = off_s;
    int base = blockIdx.x * 1024 + threadIdx.x * 4;
#pragma unroll
    for (int q = 0; q < 4; q++) {
        int i = base + q;
        if (i < n) {
            int r = g_rowptr[i] + off;
            g_rowptr[i] = r;
            g_cursor[i] = r;
        }
    }
    if (blockIdx.x == 0 && threadIdx.x == 0) g_rowptr[n] = e;
}

__global__ void scatter_kernel(const int* __restrict__ src, const int* __restrict__ dst, int e) {
    int i = (blockIdx.x * blockDim.x + threadIdx.x) * 4;
    if (i + 3 < e) {
        int4 d = *(const int4*)&dst[i];
        int4 sv = *(const int4*)&src[i];
        g_col[atomicAdd(&g_cursor[d.x], 1)] = sv.x;
        g_col[atomicAdd(&g_cursor[d.y], 1)] = sv.y;
        g_col[atomicAdd(&g_cursor[d.z], 1)] = sv.z;
        g_col[atomicAdd(&g_cursor[d.w], 1)] = sv.w;
    } else {
        for (int j = i; j < e; j++)
            g_col[atomicAdd(&g_cursor[dst[j]], 1)] = src[j];
    }
}

// ------------------- aggregation (gather, warp per node) --------------------
// Input: fp16 rows. mode 0 -> fp16 out with bias+relu (layer-1);
//                   mode 1 -> bf16 hi/lo split out (layer-2 -> tensor GEMM).
// Edge loop unrolled 8-deep (8 loads batched, 4 accumulators).

__global__ void gather_kernel(const __half* __restrict__ hin,
                              __half* __restrict__ outF16,
                              __nv_bfloat16* __restrict__ outh,
                              __nv_bfloat16* __restrict__ outl,
                              const float* __restrict__ bias, int n, int mode) {
    int w = (blockIdx.x * blockDim.x + threadIdx.x) >> 5;
    int lane = threadIdx.x & 31;
    if (w >= n) return;
    int beg = g_rowptr[w];
    int end = g_rowptr[w + 1];
    float dv = g_dinv[w];
    float4 hv = dec4(hin + (size_t)w * H, lane);
    float4 a0 = make_float4(dv * hv.x, dv * hv.y, dv * hv.z, dv * hv.w);  // self loop
    float4 a1 = make_float4(0.f, 0.f, 0.f, 0.f);
    float4 a2 = make_float4(0.f, 0.f, 0.f, 0.f);
    float4 a3 = make_float4(0.f, 0.f, 0.f, 0.f);
    for (int e0 = beg; e0 < end; e0 += 32) {
        int idx = e0 + lane;
        int c = 0;
        float dval = 0.f;
        if (idx < end) { c = g_col[idx]; dval = g_dinv[c]; }
        int m = min(32, end - e0);
        int j = 0;
        for (; j + 8 <= m; j += 8) {
            int u0 = __shfl_sync(0xffffffffu, c, j);
            int u1 = __shfl_sync(0xffffffffu, c, j + 1);
            int u2 = __shfl_sync(0xffffffffu, c, j + 2);
            int u3 = __shfl_sync(0xffffffffu, c, j + 3);
            int u4 = __shfl_sync(0xffffffffu, c, j + 4);
            int u5 = __shfl_sync(0xffffffffu, c, j + 5);
            int u6 = __shfl_sync(0xffffffffu, c, j + 6);
            int u7 = __shfl_sync(0xffffffffu, c, j + 7);
            float d0 = __shfl_sync(0xffffffffu, dval, j);
            float d1 = __shfl_sync(0xffffffffu, dval, j + 1);
            float d2 = __shfl_sync(0xffffffffu, dval, j + 2);
            float d3 = __shfl_sync(0xffffffffu, dval, j + 3);
            float d4 = __shfl_sync(0xffffffffu, dval, j + 4);
            float d5 = __shfl_sync(0xffffffffu, dval, j + 5);
            float d6 = __shfl_sync(0xffffffffu, dval, j + 6);
            float d7 = __shfl_sync(0xffffffffu, dval, j + 7);
            float4 v0 = dec4(hin + (size_t)u0 * H, lane);
            float4 v1 = dec4(hin + (size_t)u1 * H, lane);
            float4 v2 = dec4(hin + (size_t)u2 * H, lane);
            float4 v3 = dec4(hin + (size_t)u3 * H, lane);
            float4 v4 = dec4(hin + (size_t)u4 * H, lane);
            float4 v5 = dec4(hin + (size_t)u5 * H, lane);
            float4 v6 = dec4(hin + (size_t)u6 * H, lane);
            float4 v7 = dec4(hin + (size_t)u7 * H, lane);
            a0.x += d0 * v0.x; a0.y += d0 * v0.y; a0.z += d0 * v0.z; a0.w += d0 * v0.w;
            a1.x += d1 * v1.x; a1.y += d1 * v1.y; a1.z += d1 * v1.z; a1.w += d1 * v1.w;
            a2.x += d2 * v2.x; a2.y += d2 * v2.y; a2.z += d2 * v2.z; a2.w += d2 * v2.w;
            a3.x += d3 * v3.x; a3.y += d3 * v3.y; a3.z += d3 * v3.z; a3.w += d3 * v3.w;
            a0.x += d4 * v4.x; a0.y += d4 * v4.y; a0.z += d4 * v4.z; a0.w += d4 * v4.w;
            a1.x += d5 * v5.x; a1.y += d5 * v5.y; a1.z += d5 * v5.z; a1.w += d5 * v5.w;
            a2.x += d6 * v6.x; a2.y += d6 * v6.y; a2.z += d6 * v6.z; a2.w += d6 * v6.w;
            a3.x += d7 * v7.x; a3.y += d7 * v7.y; a3.z += d7 * v7.z; a3.w += d7 * v7.w;
        }
        for (; j + 4 <= m; j += 4) {
            int u0 = __shfl_sync(0xffffffffu, c, j);
            int u1 = __shfl_sync(0xffffffffu, c, j + 1);
            int u2 = __shfl_sync(0xffffffffu, c, j + 2);
            int u3 = __shfl_sync(0xffffffffu, c, j + 3);
            float d0 = __shfl_sync(0xffffffffu, dval, j);
            float d1 = __shfl_sync(0xffffffffu, dval, j + 1);
            float d2 = __shfl_sync(0xffffffffu, dval, j + 2);
            float d3 = __shfl_sync(0xffffffffu, dval, j + 3);
            float4 v0 = dec4(hin + (size_t)u0 * H, lane);
            float4 v1 = dec4(hin + (size_t)u1 * H, lane);
            float4 v2 = dec4(hin + (size_t)u2 * H, lane);
            float4 v3 = dec4(hin + (size_t)u3 * H, lane);
            a0.x += d0 * v0.x; a0.y += d0 * v0.y; a0.z += d0 * v0.z; a0.w += d0 * v0.w;
            a1.x += d1 * v1.x; a1.y += d1 * v1.y; a1.z += d1 * v1.z; a1.w += d1 * v1.w;
            a2.x += d2 * v2.x; a2.y += d2 * v2.y; a2.z += d2 * v2.z; a2.w += d2 * v2.w;
            a3.x += d3 * v3.x; a3.y += d3 * v3.y; a3.z += d3 * v3.z; a3.w += d3 * v3.w;
        }
        for (; j < m; j++) {
            int u = __shfl_sync(0xffffffffu, c, j);
            float du = __shfl_sync(0xffffffffu, dval, j);
            float4 huv = dec4(hin + (size_t)u * H, lane);
            a0.x += du * huv.x; a0.y += du * huv.y; a0.z += du * huv.z; a0.w += du * huv.w;
        }
    }
    float4 acc = make_float4((a0.x + a1.x) + (a2.x + a3.x),
                             (a0.y + a1.y) + (a2.y + a3.y),
                             (a0.z + a1.z) + (a2.z + a3.z),
                             (a0.w + a1.w) + (a2.w + a3.w));
    acc.x *= dv; acc.y *= dv; acc.z *= dv; acc.w *= dv;
    if (mode == 0) {
        float4 b4 = *(const float4*)&bias[lane * 4];
        acc.x = fmaxf(acc.x + b4.x, 0.f);
        acc.y = fmaxf(acc.y + b4.y, 0.f);
        acc.z = fmaxf(acc.z + b4.z, 0.f);
        acc.w = fmaxf(acc.w + b4.w, 0.f);
        uint2 p;
        __half2 p01 = __floats2half2_rn(acc.x, acc.y);
        __half2 p23 = __floats2half2_rn(acc.z, acc.w);
        p.x = *(uint32_t*)&p01;
        p.y = *(uint32_t*)&p23;
        *(uint2*)(outF16 + (size_t)w * H + lane * 4) = p;
    } else {
        ushort4 h, l;
        split_bf16(acc.x, h.x, l.x);
        split_bf16(acc.y, h.y, l.y);
        split_bf16(acc.z, h.z, l.z);
        split_bf16(acc.w, h.w, l.w);
        *(ushort4*)((unsigned short*)outh + (size_t)w * H + lane * 4) = h;
        *(ushort4*)((unsigned short*)outl + (size_t)w * H + lane * 4) = l;
    }
}

// ------------------------- weight folding ----------------------------------

__global__ void wprep_kernel(const float* __restrict__ W2, const float* __restrict__ W2u,
                             const float* __restrict__ Wpca, const float* __restrict__ Wbce,
                             const float* __restrict__ b2, const float* __restrict__ b2u,
                             const float* __restrict__ bpca, const float* __restrict__ bbce) {
    int k = blockIdx.x;       // 0..127 (input dim)
    int j = threadIdx.x;      // 0..127 (output dim within segment)
    int seg = blockIdx.y;     // 0..2
    float v;
    if (seg == 0) {
        v = W2[k * H + j];
    } else if (seg == 1) {
        float s = 0.f;
        for (int m = 0; m < H; m++) s += (W2[k * H + m] + W2u[k * H + m]) * Wpca[j * H + m];
        v = s;
    } else {
        float s = 0.f;
        for (int m = 0; m < H; m++) s += W2u[k * H + m] * Wbce[j * H + m];
        v = s;
    }
    unsigned short hi, lo;
    split_bf16(v, hi, lo);
    g_Wbh[k * 384 + seg * H + j] = *(__nv_bfloat16*)&hi;
    g_Wbl[k * 384 + seg * H + j] = *(__nv_bfloat16*)&lo;
    if (k == 0) {
        float b;
        if (seg == 0) {
            b = b2[j];
        } else if (seg == 1) {
            float s = 0.f;
            for (int m = 0; m < H; m++) s += (b2[m] + b2u[m]) * Wpca[j * H + m];
            b = s + bpca[j];
        } else {
            float s = 0.f;
            for (int m = 0; m < H; m++) s += b2u[m] * Wbce[j * H + m];
            b = s + bbce[j];
        }
        g_bbig[seg * H + j] = b;
    }
}

// ------------------------- bf16-split tensor GEMM --------------------------
// Block: 128 rows x (NSEG x 64 cols). A loaded ONCE; compile-time segment loop
// reloading only the W tile. 8 warps, warp tile 16x64 per segment.
// acc += Ah*Wh + Ah*Wl + Al*Wh  (fp32 accumulate) ~ fp32 accuracy.
// outF16: write fp16 (layer-1). out1f: fused out1 head from flab (segs 0-1).

#define APAD 136  // bf16 elems per padded A row (272 B; conflict-free ldmatrix)
#define WPAD 72   // bf16 elems per padded W row (144 B)

template <int NSEG>
__global__ __launch_bounds__(256)
void gemm_mma_kernel(const void* __restrict__ A0, const void* __restrict__ A1,
                     const void* __restrict__ W0, const void* __restrict__ W1p,
                     int a_fp32, int w_fp32, int ldw,
                     const float* __restrict__ bias, int n,
                     float* __restrict__ d0, float* __restrict__ d1, float* __restrict__ d2,
                     __half* __restrict__ outF16,
                     const float* __restrict__ Wh1, const float* __restrict__ bh1,
                     float* __restrict__ out1f) {
    extern __shared__ unsigned short smem[];
    unsigned short* Ah_s = smem;                    // 128 x APAD
    unsigned short* Al_s = Ah_s + 128 * APAD;
    unsigned short* Wh_s = Al_s + 128 * APAD;       // 128 x WPAD
    unsigned short* Wl_s = Wh_s + 128 * WPAD;
    float* w1_s = (float*)(Wl_s + 128 * WPAD);      // 4 x 128 (out1 head weights)

    int tid = threadIdx.x;
    int row0 = blockIdx.x * 128;

    // ---- load A once ----
    if (a_fp32) {
        const float* A = (const float*)A0;
        for (int i = tid; i < 128 * 32; i += 256) {
            int r = i >> 5;
            int c = i & 31;             // float4 chunk (4 floats)
            int gr = row0 + r;
            float4 v = make_float4(0.f, 0.f, 0.f, 0.f);
            if (gr < n) v = ((const float4*)(A + (size_t)gr * H))[c];
            ushort4 h, l;
            split_bf16(v.x, h.x, l.x);
            split_bf16(v.y, h.y, l.y);
            split_bf16(v.z, h.z, l.z);
            split_bf16(v.w, h.w, l.w);
            *(ushort4*)&Ah_s[r * APAD + c * 4] = h;
            *(ushort4*)&Al_s[r * APAD + c * 4] = l;
        }
    } else {
        const __nv_bfloat16* Ah = (const __nv_bfloat16*)A0;
        const __nv_bfloat16* Al = (const __nv_bfloat16*)A1;
        const uint4 zero4 = make_uint4(0, 0, 0, 0);
        for (int i = tid; i < 128 * 16; i += 256) {
            int r = i >> 4;
            int c = i & 15;             // 16B chunk = 8 bf16
            int gr = row0 + r;
            uint4 vh = zero4, vl = zero4;
            if (gr < n) {
                vh = ((const uint4*)(Ah + (size_t)gr * H))[c];
                vl = ((const uint4*)(Al + (size_t)gr * H))[c];
            }
            *(uint4*)&Ah_s[r * APAD + c * 8] = vh;
            *(uint4*)&Al_s[r * APAD + c * 8] = vl;
        }
    }
    if (out1f) {
        for (int i = tid; i < 512; i += 256) w1_s[i] = Wh1[i];
    }

    int lane = tid & 31;
    int warp = tid >> 5;
    int m0 = warp * 16;           // warp rows m0..m0+15
    int lrow = lane & 15;
    int lsel = lane >> 4;
    int g = lane >> 2;
    int tg = lane & 3;

    uint32_t baseAh = (uint32_t)__cvta_generic_to_shared(&Ah_s[(m0 + lrow) * APAD + lsel * 8]);
    uint32_t baseAl = (uint32_t)__cvta_generic_to_shared(&Al_s[(m0 + lrow) * APAD + lsel * 8]);
    uint32_t baseWh = (uint32_t)__cvta_generic_to_shared(&Wh_s[lrow * WPAD + lsel * 8]);
    uint32_t baseWl = (uint32_t)__cvta_generic_to_shared(&Wl_s[lrow * WPAD + lsel * 8]);

    // fused out1 state (flab rows gr0, gr1; 32 cols per thread across segs 0-1)
    float ss_a = 0.f, ss_b = 0.f;
    float pa[4] = {0.f, 0.f, 0.f, 0.f};
    float pb[4] = {0.f, 0.f, 0.f, 0.f};

    for (int seg = 0; seg < NSEG; seg++) {
        int colOff = seg * 64;

        // ---- load W tile for this segment ----
        if (w_fp32) {
            const float* W = (const float*)W0;
            for (int i = tid; i < 128 * 16; i += 256) {
                int k = i >> 4;
                int c = i & 15;
                float4 v = ((const float4*)(W + (size_t)k * ldw + colOff))[c];
                ushort4 h, l;
                split_bf16(v.x, h.x, l.x);
                split_bf16(v.y, h.y, l.y);
                split_bf16(v.z, h.z, l.z);
                split_bf16(v.w, h.w, l.w);
                *(ushort4*)&Wh_s[k * WPAD + c * 4] = h;
                *(ushort4*)&Wl_s[k * WPAD + c * 4] = l;
            }
        } else {
            const __nv_bfloat16* Wh = (const __nv_bfloat16*)W0;
            const __nv_bfloat16* Wl = (const __nv_bfloat16*)W1p;
            for (int i = tid; i < 128 * 8; i += 256) {
                int k = i >> 3;
                int c = i & 7;
                *(uint4*)&Wh_s[k * WPAD + c * 8] =
                    ((const uint4*)(Wh + (size_t)k * ldw + colOff))[c];
                *(uint4*)&Wl_s[k * WPAD + c * 8] =
                    ((const uint4*)(Wl + (size_t)k * ldw + colOff))[c];
            }
        }
        __syncthreads();

        float acc[8][4];
#pragma unroll
        for (int nt = 0; nt < 8; nt++)
#pragma unroll
            for (int q = 0; q < 4; q++) acc[nt][q] = 0.f;

        for (int k0 = 0; k0 < 128; k0 += 16) {
            uint32_t ah[4], al[4], wh[8][2], wl[8][2];
            ldsm4(ah[0], ah[1], ah[2], ah[3], baseAh + (uint32_t)k0 * 2);
            ldsm4(al[0], al[1], al[2], al[3], baseAl + (uint32_t)k0 * 2);
#pragma unroll
            for (int nt2 = 0; nt2 < 4; nt2++) {
                uint32_t off = (uint32_t)(k0 * WPAD + nt2 * 16) * 2;
                ldsm4t(wh[2 * nt2][0], wh[2 * nt2][1], wh[2 * nt2 + 1][0], wh[2 * nt2 + 1][1],
                       baseWh + off);
                ldsm4t(wl[2 * nt2][0], wl[2 * nt2][1], wl[2 * nt2 + 1][0], wl[2 * nt2 + 1][1],
                       baseWl + off);
            }
#pragma unroll
            for (int nt = 0; nt < 8; nt++) {
                mma_bf16(acc[nt], ah, wh[nt]);
                mma_bf16(acc[nt], ah, wl[nt]);
                mma_bf16(acc[nt], al, wh[nt]);
            }
        }

        // ---- epilogue for this segment ----
        if (outF16) {
#pragma unroll
            for (int nt = 0; nt < 8; nt++) {
                int col = colOff + nt * 8 + 2 * tg;
                int gr0 = row0 + m0 + g;
                if (gr0 < n) {
                    __half2 o = __floats2half2_rn(acc[nt][0], acc[nt][1]);
                    *(__half2*)(outF16 + (size_t)gr0 * H + col) = o;
                }
                int gr1 = gr0 + 8;
                if (gr1 < n) {
                    __half2 o = __floats2half2_rn(acc[nt][2], acc[nt][3]);
                    *(__half2*)(outF16 + (size_t)gr1 * H + col) = o;
                }
            }
        } else {
            int oseg = colOff >> 7;
            float* dst = (oseg == 0) ? d0 : ((oseg == 1) ? d1 : d2);
            int jbase = colOff & 127;
            int flabSeg = (out1f != nullptr) && (oseg == 0);
#pragma unroll
            for (int nt = 0; nt < 8; nt++) {
                int colL = nt * 8 + 2 * tg;
                float bx = 0.f, by = 0.f;
                if (bias) { bx = bias[colOff + colL]; by = bias[colOff + colL + 1]; }
                int gr0 = row0 + m0 + g;
                if (gr0 < n) {
                    float2 o = make_float2(acc[nt][0] + bx, acc[nt][1] + by);
                    *(float2*)&dst[(size_t)gr0 * H + jbase + colL] = o;
                    if (flabSeg) {
                        int col = colOff + colL;
                        ss_a += o.x * o.x + o.y * o.y;
#pragma unroll
                        for (int jj = 0; jj < 4; jj++)
                            pa[jj] += o.x * w1_s[jj * 128 + col] + o.y * w1_s[jj * 128 + col + 1];
                    }
                }
                int gr1 = gr0 + 8;
                if (gr1 < n) {
                    float2 o = make_float2(acc[nt][2] + bx, acc[nt][3] + by);
                    *(float2*)&dst[(size_t)gr1 * H + jbase + colL] = o;
                    if (flabSeg) {
                        int col = colOff + colL;
                        ss_b += o.x * o.x + o.y * o.y;
#pragma unroll
                        for (int jj = 0; jj < 4; jj++)
                            pb[jj] += o.x * w1_s[jj * 128 + col] + o.y * w1_s[jj * 128 + col + 1];
                    }
                }
            }
        }
        __syncthreads();   // W smem reused next segment
    }

    // ---- fused out1 finalize: reduce over the 4-lane tg group ----
    if (out1f) {
#pragma unroll
        for (int off = 1; off < 4; off <<= 1) {
            ss_a += __shfl_xor_sync(0xffffffffu, ss_a, off);
            ss_b += __shfl_xor_sync(0xffffffffu, ss_b, off);
#pragma unroll
            for (int jj = 0; jj < 4; jj++) {
                pa[jj] += __shfl_xor_sync(0xffffffffu, pa[jj], off);
                pb[jj] += __shfl_xor_sync(0xffffffffu, pb[jj], off);
            }
        }
        if (tg == 0) {
            int gr0 = row0 + m0 + g;
            if (gr0 < n) {
                float inv = 10.f / fmaxf(sqrtf(ss_a), 1e-12f);
#pragma unroll
                for (int jj = 0; jj < 4; jj++)
                    out1f[(size_t)gr0 * 4 + jj] = pa[jj] * inv + bh1[jj] * 10.f;
            }
            int gr1 = gr0 + 8;
            if (gr1 < n) {
                float inv = 10.f / fmaxf(sqrtf(ss_b), 1e-12f);
#pragma unroll
                for (int jj = 0; jj < 4; jj++)
                    out1f[(size_t)gr1 * 4 + jj] = pb[jj] * inv + bh1[jj] * 10.f;
            }
        }
    }
}

// ------------------------- launch ------------------------------------------

extern "C" void kernel_launch(void* const* d_in, const int* in_sizes, int n_in,
                              void* d_out, int out_size) {
    const float* x    = (const float*)d_in[0];
    const int*   ei   = (const int*)d_in[1];
    const float* W1   = (const float*)d_in[2];
    const float* b1   = (const float*)d_in[3];
    const float* W2   = (const float*)d_in[4];
    const float* b2   = (const float*)d_in[5];
    const float* W2u  = (const float*)d_in[6];
    const float* b2u  = (const float*)d_in[7];
    const float* Wh1  = (const float*)d_in[8];
    const float* bh1  = (const float*)d_in[9];
    const float* Wpca = (const float*)d_in[10];
    const float* bpca = (const float*)d_in[11];
    const float* Wbce = (const float*)d_in[12];
    const float* bbce = (const float*)d_in[13];

    int n = in_sizes[0] / H;
    int e = in_sizes[1] / 2;
    const int* src = ei;
    const int* dst = ei + e;

    float* out  = (float*)d_out;
    float* out1 = out;
    float* opca = out + (size_t)n * 4;
    float* obce = opca + (size_t)n * H;
    float* flab = obce + (size_t)n * H;

    void *p_h0f, *p_hf, *p_aggh, *p_aggl, *p_Wbh, *p_Wbl, *p_bbig;
    cudaGetSymbolAddress(&p_h0f, g_h0f);
    cudaGetSymbolAddress(&p_hf, g_hf);
    cudaGetSymbolAddress(&p_aggh, g_aggh);
    cudaGetSymbolAddress(&p_aggl, g_aggl);
    cudaGetSymbolAddress(&p_Wbh, g_Wbh);
    cudaGetSymbolAddress(&p_Wbl, g_Wbl);
    cudaGetSymbolAddress(&p_bbig, g_bbig);

    const int smem_gemm = (2 * 128 * APAD + 2 * 128 * WPAD) * 2 + 4 * 128 * 4;  // 108544 B
    cudaFuncSetAttribute(gemm_mma_kernel<2>, cudaFuncAttributeMaxDynamicSharedMemorySize, smem_gemm);
    cudaFuncSetAttribute(gemm_mma_kernel<6>, cudaFuncAttributeMaxDynamicSharedMemorySize, smem_gemm);

    int nb_n = (n + 255) / 256;
    int nb_e4 = (e + 1023) / 1024;     // 4 edges per thread
    int nb_w = (n + 7) / 8;            // warp-per-node, 256 threads = 8 warps
    int nb_g = (n + 127) / 128;        // gemm row tiles
    int nb_s = (n + 1023) / 1024;      // scan blocks

    // graph prep
    zero_deg_kernel<<<nb_n, 256>>>(n);
    hist_kernel<<<nb_e4, 256>>>(dst, e);
    blockscan_kernel<<<nb_s, 256>>>(n);    // also emits dinv
    addoff_kernel<<<nb_s, 256>>>(n, e);    // fused bsum prefix + offset add
    scatter_kernel<<<nb_e4, 256>>>(src, dst, e);

    // layer 1: h0 = x @ W1 (fp32 in, split in-kernel), fp16 out; 2 segs in-kernel
    gemm_mma_kernel<2><<<nb_g, 256, smem_gemm>>>(
        x, nullptr, W1, nullptr, 1, 1, H, nullptr, n,
        nullptr, nullptr, nullptr, (__half*)p_h0f, nullptr, nullptr, nullptr);
    // h = relu(Agg(h0) + b1), fp16 out
    gather_kernel<<<nb_w, 256>>>((const __half*)p_h0f, (__half*)p_hf,
                                 nullptr, nullptr, b1, n, 0);

    // fold layer-2 + head weights (bf16 split)
    wprep_kernel<<<dim3(H, 3), H>>>(W2, W2u, Wpca, Wbce, b2, b2u, bpca, bbce);

    // layer 2: agg = Agg(h) (bf16 split out) ; fused GEMM (6 segs) + out1 head
    gather_kernel<<<nb_w, 256>>>((const __half*)p_hf, nullptr,
                                 (__nv_bfloat16*)p_aggh, (__nv_bfloat16*)p_aggl,
                                 nullptr, n, 1);
    gemm_mma_kernel<6><<<nb_g, 256, smem_gemm>>>(
        (const void*)p_aggh, (const void*)p_aggl, (const void*)p_Wbh, (const void*)p_Wbl,
        0, 0, 384, (const float*)p_bbig, n, flab, opca, obce, nullptr,
        Wh1, bh1, out1);
}

// round 17
// speedup vs baseline: 1.0769x; 1.0769x over previous
#include <cuda_runtime.h>
#include <cuda_bf16.h>
#include <cuda_fp16.h>
#include <cstdint>
#include <math.h>

// ---------------------------------------------------------------------------
// Res_GCN: 2-layer GCN + heads, bf16-split tensor-core GEMMs (mma.sync).
// Features h0, h stored fp16 (256 B/row). GEMM loads A once per row-tile,
// compile-time NSEG column-segment loop. (R12 config + tree-reduce addoff.)
//   h   = relu(Agg(x@W1) + b1)
//   agg = Agg(h)
//   feat_label = agg@W2 + b2 ; out_pca = agg@((W2+W2u)Wpca^T)+b' ;
//   out_bce = agg@(W2u Wbce^T)+b'' ; out1 = ((flab/||.||)@Wh1^T + bh1)/0.1
// ---------------------------------------------------------------------------

#define MAXN 50000
#define MAXE 800000
#define H 128

__device__ __half g_h0f[MAXN * H];            // x @ W1 (fp16)
__device__ __half g_hf[MAXN * H];             // relu(Agg(h0)+b1) (fp16)
__device__ __nv_bfloat16 g_aggh[MAXN * H];    // Agg(h) hi
__device__ __nv_bfloat16 g_aggl[MAXN * H];    // Agg(h) lo
__device__ __nv_bfloat16 g_Wbh[H * 384];      // folded layer-2 weights hi (K-major)
__device__ __nv_bfloat16 g_Wbl[H * 384];      // folded layer-2 weights lo
__device__ float g_bbig[384];
__device__ float g_dinv[MAXN];
__device__ int   g_deg[MAXN];
__device__ int   g_rowptr[MAXN + 1];
__device__ int   g_cursor[MAXN];
__device__ int   g_col[MAXE];
__device__ int   g_bsum[64];

// ------------------------- helpers -----------------------------------------

__device__ __forceinline__ void split_bf16(float a, unsigned short& hi, unsigned short& lo) {
    __nv_bfloat16 h = __float2bfloat16_rn(a);
    float r = a - __bfloat162float(h);
    __nv_bfloat16 l = __float2bfloat16_rn(r);
    hi = *(unsigned short*)&h;
    lo = *(unsigned short*)&l;
}

__device__ __forceinline__ float4 dec4(const __half* __restrict__ row, int lane) {
    uint2 v = *(const uint2*)(row + lane * 4);       // 8 B: 4 fp16
    float2 f01 = __half22float2(*(__half2*)&v.x);
    float2 f23 = __half22float2(*(__half2*)&v.y);
    return make_float4(f01.x, f01.y, f23.x, f23.y);
}

__device__ __forceinline__ void ldsm4(uint32_t& r0, uint32_t& r1, uint32_t& r2, uint32_t& r3,
                                      uint32_t addr) {
    asm volatile("ldmatrix.sync.aligned.m8n8.x4.shared.b16 {%0,%1,%2,%3}, [%4];\n"
                 : "=r"(r0), "=r"(r1), "=r"(r2), "=r"(r3) : "r"(addr));
}

__device__ __forceinline__ void ldsm4t(uint32_t& r0, uint32_t& r1, uint32_t& r2, uint32_t& r3,
                                       uint32_t addr) {
    asm volatile("ldmatrix.sync.aligned.m8n8.x4.trans.shared.b16 {%0,%1,%2,%3}, [%4];\n"
                 : "=r"(r0), "=r"(r1), "=r"(r2), "=r"(r3) : "r"(addr));
}

__device__ __forceinline__ void mma_bf16(float* d, const uint32_t* a, const uint32_t* b) {
    asm volatile("mma.sync.aligned.m16n8k16.row.col.f32.bf16.bf16.f32 "
                 "{%0,%1,%2,%3}, {%4,%5,%6,%7}, {%8,%9}, {%0,%1,%2,%3};\n"
                 : "+f"(d[0]), "+f"(d[1]), "+f"(d[2]), "+f"(d[3])
                 : "r"(a[0]), "r"(a[1]), "r"(a[2]), "r"(a[3]), "r"(b[0]), "r"(b[1]));
}

// ------------------------- graph prep --------------------------------------

__global__ void zero_deg_kernel(int n) {
    int i = blockIdx.x * blockDim.x + threadIdx.x;
    if (i < n) g_deg[i] = 0;
}

__global__ void hist_kernel(const int* __restrict__ dst, int e) {
    int i = (blockIdx.x * blockDim.x + threadIdx.x) * 4;
    if (i + 3 < e) {
        int4 d = *(const int4*)&dst[i];
        atomicAdd(&g_deg[d.x], 1);
        atomicAdd(&g_deg[d.y], 1);
        atomicAdd(&g_deg[d.z], 1);
        atomicAdd(&g_deg[d.w], 1);
    } else {
        for (int j = i; j < e; j++) atomicAdd(&g_deg[dst[j]], 1);
    }
}

// block-local scan: 256 threads x 4 items = 1024 per block; also emits dinv
__global__ void blockscan_kernel(int n) {
    __shared__ int s[256];
    int t = threadIdx.x;
    int base = blockIdx.x * 1024 + t * 4;
    int v0 = (base + 0 < n) ? g_deg[base + 0] : 0;
    int v1 = (base + 1 < n) ? g_deg[base + 1] : 0;
    int v2 = (base + 2 < n) ? g_deg[base + 2] : 0;
    int v3 = (base + 3 < n) ? g_deg[base + 3] : 0;
    if (base + 0 < n) g_dinv[base + 0] = rsqrtf((float)(v0 + 1));
    if (base + 1 < n) g_dinv[base + 1] = rsqrtf((float)(v1 + 1));
    if (base + 2 < n) g_dinv[base + 2] = rsqrtf((float)(v2 + 1));
    if (base + 3 < n) g_dinv[base + 3] = rsqrtf((float)(v3 + 1));
    int sum = v0 + v1 + v2 + v3;
    s[t] = sum;
    __syncthreads();
    for (int off = 1; off < 256; off <<= 1) {
        int tv = (t >= off) ? s[t - off] : 0;
        __syncthreads();
        s[t] += tv;
        __syncthreads();
    }
    int run = s[t] - sum;
    if (base + 0 < n) { g_rowptr[base + 0] = run; } run += v0;
    if (base + 1 < n) { g_rowptr[base + 1] = run; } run += v1;
    if (base + 2 < n) { g_rowptr[base + 2] = run; } run += v2;
    if (base + 3 < n) { g_rowptr[base + 3] = run; }
    if (t == 255) g_bsum[blockIdx.x] = s[255];
}

// addoff: one block per 1024 nodes (same tiling as blockscan). Offset for this
// block = sum of preceding block sums, computed by a 64-wide tree reduction.
__global__ void addoff_kernel(int n, int e) {
    __shared__ int s[64];
    int t = threadIdx.x;
    if (t < 64) s[t] = (t < (int)blockIdx.x) ? g_bsum[t] : 0;
    __syncthreads();
    if (t < 32) s[t] += s[t + 32];
    __syncthreads();
    if (t < 16) s[t] += s[t + 16];
    __syncthreads();
    if (t < 8) s[t] += s[t + 8];
    __syncthreads();
    if (t < 4) s[t] += s[t + 4];
    __syncthreads();
    if (t < 2) s[t] += s[t + 2];
    __syncthreads();
    if (t < 1) s[t] += s[t + 1];
    __syncthreads();
    int off = s[0];
    int base = blockIdx.x * 1024 + t * 4;
#pragma unroll
    for (int q = 0; q < 4; q++) {
        int i = base + q;
        if (i < n) {
            int r = g_rowptr[i] + off;
            g_rowptr[i] = r;
            g_cursor[i] = r;
        }
    }
    if (blockIdx.x == 0 && t == 0) g_rowptr[n] = e;
}

__global__ void scatter_kernel(const int* __restrict__ src, const int* __restrict__ dst, int e) {
    int i = (blockIdx.x * blockDim.x + threadIdx.x) * 4;
    if (i + 3 < e) {
        int4 d = *(const int4*)&dst[i];
        int4 sv = *(const int4*)&src[i];
        g_col[atomicAdd(&g_cursor[d.x], 1)] = sv.x;
        g_col[atomicAdd(&g_cursor[d.y], 1)] = sv.y;
        g_col[atomicAdd(&g_cursor[d.z], 1)] = sv.z;
        g_col[atomicAdd(&g_cursor[d.w], 1)] = sv.w;
    } else {
        for (int j = i; j < e; j++)
            g_col[atomicAdd(&g_cursor[dst[j]], 1)] = src[j];
    }
}

// ------------------- aggregation (gather, warp per node) --------------------
// Input: fp16 rows. mode 0 -> fp16 out with bias+relu (layer-1);
//                   mode 1 -> bf16 hi/lo split out (layer-2 -> tensor GEMM).

__global__ void gather_kernel(const __half* __restrict__ hin,
                              __half* __restrict__ outF16,
                              __nv_bfloat16* __restrict__ outh,
                              __nv_bfloat16* __restrict__ outl,
                              const float* __restrict__ bias, int n, int mode) {
    int w = (blockIdx.x * blockDim.x + threadIdx.x) >> 5;
    int lane = threadIdx.x & 31;
    if (w >= n) return;
    int beg = g_rowptr[w];
    int end = g_rowptr[w + 1];
    float dv = g_dinv[w];
    float4 hv = dec4(hin + (size_t)w * H, lane);
    float4 a0 = make_float4(dv * hv.x, dv * hv.y, dv * hv.z, dv * hv.w);  // self loop
    float4 a1 = make_float4(0.f, 0.f, 0.f, 0.f);
    float4 a2 = make_float4(0.f, 0.f, 0.f, 0.f);
    float4 a3 = make_float4(0.f, 0.f, 0.f, 0.f);
    for (int e0 = beg; e0 < end; e0 += 32) {
        int idx = e0 + lane;
        int c = 0;
        float dval = 0.f;
        if (idx < end) { c = g_col[idx]; dval = g_dinv[c]; }
        int m = min(32, end - e0);
        int j = 0;
        for (; j + 4 <= m; j += 4) {
            int u0 = __shfl_sync(0xffffffffu, c, j);
            int u1 = __shfl_sync(0xffffffffu, c, j + 1);
            int u2 = __shfl_sync(0xffffffffu, c, j + 2);
            int u3 = __shfl_sync(0xffffffffu, c, j + 3);
            float d0 = __shfl_sync(0xffffffffu, dval, j);
            float d1 = __shfl_sync(0xffffffffu, dval, j + 1);
            float d2 = __shfl_sync(0xffffffffu, dval, j + 2);
            float d3 = __shfl_sync(0xffffffffu, dval, j + 3);
            float4 v0 = dec4(hin + (size_t)u0 * H, lane);
            float4 v1 = dec4(hin + (size_t)u1 * H, lane);
            float4 v2 = dec4(hin + (size_t)u2 * H, lane);
            float4 v3 = dec4(hin + (size_t)u3 * H, lane);
            a0.x += d0 * v0.x; a0.y += d0 * v0.y; a0.z += d0 * v0.z; a0.w += d0 * v0.w;
            a1.x += d1 * v1.x; a1.y += d1 * v1.y; a1.z += d1 * v1.z; a1.w += d1 * v1.w;
            a2.x += d2 * v2.x; a2.y += d2 * v2.y; a2.z += d2 * v2.z; a2.w += d2 * v2.w;
            a3.x += d3 * v3.x; a3.y += d3 * v3.y; a3.z += d3 * v3.z; a3.w += d3 * v3.w;
        }
        for (; j < m; j++) {
            int u = __shfl_sync(0xffffffffu, c, j);
            float du = __shfl_sync(0xffffffffu, dval, j);
            float4 huv = dec4(hin + (size_t)u * H, lane);
            a0.x += du * huv.x; a0.y += du * huv.y; a0.z += du * huv.z; a0.w += du * huv.w;
        }
    }
    float4 acc = make_float4((a0.x + a1.x) + (a2.x + a3.x),
                             (a0.y + a1.y) + (a2.y + a3.y),
                             (a0.z + a1.z) + (a2.z + a3.z),
                             (a0.w + a1.w) + (a2.w + a3.w));
    acc.x *= dv; acc.y *= dv; acc.z *= dv; acc.w *= dv;
    if (mode == 0) {
        float4 b4 = *(const float4*)&bias[lane * 4];
        acc.x = fmaxf(acc.x + b4.x, 0.f);
        acc.y = fmaxf(acc.y + b4.y, 0.f);
        acc.z = fmaxf(acc.z + b4.z, 0.f);
        acc.w = fmaxf(acc.w + b4.w, 0.f);
        uint2 p;
        __half2 p01 = __floats2half2_rn(acc.x, acc.y);
        __half2 p23 = __floats2half2_rn(acc.z, acc.w);
        p.x = *(uint32_t*)&p01;
        p.y = *(uint32_t*)&p23;
        *(uint2*)(outF16 + (size_t)w * H + lane * 4) = p;
    } else {
        ushort4 h, l;
        split_bf16(acc.x, h.x, l.x);
        split_bf16(acc.y, h.y, l.y);
        split_bf16(acc.z, h.z, l.z);
        split_bf16(acc.w, h.w, l.w);
        *(ushort4*)((unsigned short*)outh + (size_t)w * H + lane * 4) = h;
        *(ushort4*)((unsigned short*)outl + (size_t)w * H + lane * 4) = l;
    }
}

// ------------------------- weight folding ----------------------------------

__global__ void wprep_kernel(const float* __restrict__ W2, const float* __restrict__ W2u,
                             const float* __restrict__ Wpca, const float* __restrict__ Wbce,
                             const float* __restrict__ b2, const float* __restrict__ b2u,
                             const float* __restrict__ bpca, const float* __restrict__ bbce) {
    int k = blockIdx.x;       // 0..127 (input dim)
    int j = threadIdx.x;      // 0..127 (output dim within segment)
    int seg = blockIdx.y;     // 0..2
    float v;
    if (seg == 0) {
        v = W2[k * H + j];
    } else if (seg == 1) {
        float s = 0.f;
        for (int m = 0; m < H; m++) s += (W2[k * H + m] + W2u[k * H + m]) * Wpca[j * H + m];
        v = s;
    } else {
        float s = 0.f;
        for (int m = 0; m < H; m++) s += W2u[k * H + m] * Wbce[j * H + m];
        v = s;
    }
    unsigned short hi, lo;
    split_bf16(v, hi, lo);
    g_Wbh[k * 384 + seg * H + j] = *(__nv_bfloat16*)&hi;
    g_Wbl[k * 384 + seg * H + j] = *(__nv_bfloat16*)&lo;
    if (k == 0) {
        float b;
        if (seg == 0) {
            b = b2[j];
        } else if (seg == 1) {
            float s = 0.f;
            for (int m = 0; m < H; m++) s += (b2[m] + b2u[m]) * Wpca[j * H + m];
            b = s + bpca[j];
        } else {
            float s = 0.f;
            for (int m = 0; m < H; m++) s += b2u[m] * Wbce[j * H + m];
            b = s + bbce[j];
        }
        g_bbig[seg * H + j] = b;
    }
}

// ------------------------- bf16-split tensor GEMM --------------------------
// Block: 128 rows x (NSEG x 64 cols). A loaded ONCE; compile-time segment loop
// reloading only the W tile. 8 warps, warp tile 16x64 per segment.
// acc += Ah*Wh + Ah*Wl + Al*Wh  (fp32 accumulate) ~ fp32 accuracy.
// a_fp32/w_fp32: operand arrives fp32, split during smem fill.
// outF16: if non-null, write fp16 (layer-1 h0 path) instead of fp32.

#define APAD 136  // bf16 elems per padded A row (272 B; conflict-free ldmatrix)
#define WPAD 72   // bf16 elems per padded W row (144 B)

template <int NSEG>
__global__ __launch_bounds__(256)
void gemm_mma_kernel(const void* __restrict__ A0, const void* __restrict__ A1,
                     const void* __restrict__ W0, const void* __restrict__ W1p,
                     int a_fp32, int w_fp32, int ldw,
                     const float* __restrict__ bias, int n,
                     float* __restrict__ d0, float* __restrict__ d1, float* __restrict__ d2,
                     __half* __restrict__ outF16) {
    extern __shared__ unsigned short smem[];
    unsigned short* Ah_s = smem;                    // 128 x APAD
    unsigned short* Al_s = Ah_s + 128 * APAD;
    unsigned short* Wh_s = Al_s + 128 * APAD;       // 128 x WPAD
    unsigned short* Wl_s = Wh_s + 128 * WPAD;

    int tid = threadIdx.x;
    int row0 = blockIdx.x * 128;

    // ---- load A once ----
    if (a_fp32) {
        const float* A = (const float*)A0;
        for (int i = tid; i < 128 * 32; i += 256) {
            int r = i >> 5;
            int c = i & 31;             // float4 chunk (4 floats)
            int gr = row0 + r;
            float4 v = make_float4(0.f, 0.f, 0.f, 0.f);
            if (gr < n) v = ((const float4*)(A + (size_t)gr * H))[c];
            ushort4 h, l;
            split_bf16(v.x, h.x, l.x);
            split_bf16(v.y, h.y, l.y);
            split_bf16(v.z, h.z, l.z);
            split_bf16(v.w, h.w, l.w);
            *(ushort4*)&Ah_s[r * APAD + c * 4] = h;
            *(ushort4*)&Al_s[r * APAD + c * 4] = l;
        }
    } else {
        const __nv_bfloat16* Ah = (const __nv_bfloat16*)A0;
        const __nv_bfloat16* Al = (const __nv_bfloat16*)A1;
        const uint4 zero4 = make_uint4(0, 0, 0, 0);
        for (int i = tid; i < 128 * 16; i += 256) {
            int r = i >> 4;
            int c = i & 15;             // 16B chunk = 8 bf16
            int gr = row0 + r;
            uint4 vh = zero4, vl = zero4;
            if (gr < n) {
                vh = ((const uint4*)(Ah + (size_t)gr * H))[c];
                vl = ((const uint4*)(Al + (size_t)gr * H))[c];
            }
            *(uint4*)&Ah_s[r * APAD + c * 8] = vh;
            *(uint4*)&Al_s[r * APAD + c * 8] = vl;
        }
    }

    int lane = tid & 31;
    int warp = tid >> 5;
    int m0 = warp * 16;           // warp rows m0..m0+15
    int lrow = lane & 15;
    int lsel = lane >> 4;
    int g = lane >> 2;
    int tg = lane & 3;

    uint32_t baseAh = (uint32_t)__cvta_generic_to_shared(&Ah_s[(m0 + lrow) * APAD + lsel * 8]);
    uint32_t baseAl = (uint32_t)__cvta_generic_to_shared(&Al_s[(m0 + lrow) * APAD + lsel * 8]);
    uint32_t baseWh = (uint32_t)__cvta_generic_to_shared(&Wh_s[lrow * WPAD + lsel * 8]);
    uint32_t baseWl = (uint32_t)__cvta_generic_to_shared(&Wl_s[lrow * WPAD + lsel * 8]);

    for (int seg = 0; seg < NSEG; seg++) {
        int colOff = seg * 64;

        // ---- load W tile for this segment ----
        if (w_fp32) {
            const float* W = (const float*)W0;
            for (int i = tid; i < 128 * 16; i += 256) {
                int k = i >> 4;
                int c = i & 15;
                float4 v = ((const float4*)(W + (size_t)k * ldw + colOff))[c];
                ushort4 h, l;
                split_bf16(v.x, h.x, l.x);
                split_bf16(v.y, h.y, l.y);
                split_bf16(v.z, h.z, l.z);
                split_bf16(v.w, h.w, l.w);
                *(ushort4*)&Wh_s[k * WPAD + c * 4] = h;
                *(ushort4*)&Wl_s[k * WPAD + c * 4] = l;
            }
        } else {
            const __nv_bfloat16* Wh = (const __nv_bfloat16*)W0;
            const __nv_bfloat16* Wl = (const __nv_bfloat16*)W1p;
            for (int i = tid; i < 128 * 8; i += 256) {
                int k = i >> 3;
                int c = i & 7;
                *(uint4*)&Wh_s[k * WPAD + c * 8] =
                    ((const uint4*)(Wh + (size_t)k * ldw + colOff))[c];
                *(uint4*)&Wl_s[k * WPAD + c * 8] =
                    ((const uint4*)(Wl + (size_t)k * ldw + colOff))[c];
            }
        }
        __syncthreads();

        float acc[8][4];
#pragma unroll
        for (int nt = 0; nt < 8; nt++)
#pragma unroll
            for (int q = 0; q < 4; q++) acc[nt][q] = 0.f;

        for (int k0 = 0; k0 < 128; k0 += 16) {
            uint32_t ah[4], al[4], wh[8][2], wl[8][2];
            ldsm4(ah[0], ah[1], ah[2], ah[3], baseAh + (uint32_t)k0 * 2);
            ldsm4(al[0], al[1], al[2], al[3], baseAl + (uint32_t)k0 * 2);
#pragma unroll
            for (int nt2 = 0; nt2 < 4; nt2++) {
                uint32_t off = (uint32_t)(k0 * WPAD + nt2 * 16) * 2;
                ldsm4t(wh[2 * nt2][0], wh[2 * nt2][1], wh[2 * nt2 + 1][0], wh[2 * nt2 + 1][1],
                       baseWh + off);
                ldsm4t(wl[2 * nt2][0], wl[2 * nt2][1], wl[2 * nt2 + 1][0], wl[2 * nt2 + 1][1],
                       baseWl + off);
            }
#pragma unroll
            for (int nt = 0; nt < 8; nt++) {
                mma_bf16(acc[nt], ah, wh[nt]);
                mma_bf16(acc[nt], ah, wl[nt]);
                mma_bf16(acc[nt], al, wh[nt]);
            }
        }

        // ---- epilogue for this segment ----
        if (outF16) {
#pragma unroll
            for (int nt = 0; nt < 8; nt++) {
                int col = colOff + nt * 8 + 2 * tg;
                int gr0 = row0 + m0 + g;
                if (gr0 < n) {
                    __half2 o = __floats2half2_rn(acc[nt][0], acc[nt][1]);
                    *(__half2*)(outF16 + (size_t)gr0 * H + col) = o;
                }
                int gr1 = gr0 + 8;
                if (gr1 < n) {
                    __half2 o = __floats2half2_rn(acc[nt][2], acc[nt][3]);
                    *(__half2*)(outF16 + (size_t)gr1 * H + col) = o;
                }
            }
        } else {
            int oseg = colOff >> 7;
            float* dst = (oseg == 0) ? d0 : ((oseg == 1) ? d1 : d2);
            int jbase = colOff & 127;
#pragma unroll
            for (int nt = 0; nt < 8; nt++) {
                int colL = nt * 8 + 2 * tg;
                float bx = 0.f, by = 0.f;
                if (bias) { bx = bias[colOff + colL]; by = bias[colOff + colL + 1]; }
                int gr0 = row0 + m0 + g;
                if (gr0 < n) {
                    float2 o = make_float2(acc[nt][0] + bx, acc[nt][1] + by);
                    *(float2*)&dst[(size_t)gr0 * H + jbase + colL] = o;
                }
                int gr1 = gr0 + 8;
                if (gr1 < n) {
                    float2 o = make_float2(acc[nt][2] + bx, acc[nt][3] + by);
                    *(float2*)&dst[(size_t)gr1 * H + jbase + colL] = o;
                }
            }
        }
        __syncthreads();   // W smem reused next segment
    }
}

// ------------------------- out1 head ---------------------------------------

__global__ void out1_kernel(const float* __restrict__ fl, const float* __restrict__ Wh1,
                            const float* __restrict__ bh1, float* __restrict__ out1, int n) {
    int w = (blockIdx.x * blockDim.x + threadIdx.x) >> 5;
    int lane = threadIdx.x & 31;
    if (w >= n) return;
    float4 f = *(const float4*)&fl[(size_t)w * H + lane * 4];
    float ss = f.x * f.x + f.y * f.y + f.z * f.z + f.w * f.w;
#pragma unroll
    for (int off = 16; off > 0; off >>= 1) ss += __shfl_xor_sync(0xffffffffu, ss, off);
    float nrm = fmaxf(sqrtf(ss), 1e-12f);
    float inv = 10.f / nrm;
#pragma unroll
    for (int j = 0; j < 4; j++) {
        float4 wv = *(const float4*)&Wh1[j * H + lane * 4];
        float p = f.x * wv.x + f.y * wv.y + f.z * wv.z + f.w * wv.w;
#pragma unroll
        for (int off = 16; off > 0; off >>= 1) p += __shfl_xor_sync(0xffffffffu, p, off);
        if (lane == 0) out1[(size_t)w * 4 + j] = p * inv + bh1[j] * 10.f;
    }
}

// ------------------------- launch ------------------------------------------

extern "C" void kernel_launch(void* const* d_in, const int* in_sizes, int n_in,
                              void* d_out, int out_size) {
    const float* x    = (const float*)d_in[0];
    const int*   ei   = (const int*)d_in[1];
    const float* W1   = (const float*)d_in[2];
    const float* b1   = (const float*)d_in[3];
    const float* W2   = (const float*)d_in[4];
    const float* b2   = (const float*)d_in[5];
    const float* W2u  = (const float*)d_in[6];
    const float* b2u  = (const float*)d_in[7];
    const float* Wh1  = (const float*)d_in[8];
    const float* bh1  = (const float*)d_in[9];
    const float* Wpca = (const float*)d_in[10];
    const float* bpca = (const float*)d_in[11];
    const float* Wbce = (const float*)d_in[12];
    const float* bbce = (const float*)d_in[13];

    int n = in_sizes[0] / H;
    int e = in_sizes[1] / 2;
    const int* src = ei;
    const int* dst = ei + e;

    float* out  = (float*)d_out;
    float* out1 = out;
    float* opca = out + (size_t)n * 4;
    float* obce = opca + (size_t)n * H;
    float* flab = obce + (size_t)n * H;

    void *p_h0f, *p_hf, *p_aggh, *p_aggl, *p_Wbh, *p_Wbl, *p_bbig;
    cudaGetSymbolAddress(&p_h0f, g_h0f);
    cudaGetSymbolAddress(&p_hf, g_hf);
    cudaGetSymbolAddress(&p_aggh, g_aggh);
    cudaGetSymbolAddress(&p_aggl, g_aggl);
    cudaGetSymbolAddress(&p_Wbh, g_Wbh);
    cudaGetSymbolAddress(&p_Wbl, g_Wbl);
    cudaGetSymbolAddress(&p_bbig, g_bbig);

    const int smem_gemm = (2 * 128 * APAD + 2 * 128 * WPAD) * 2;  // 106496 B
    cudaFuncSetAttribute(gemm_mma_kernel<2>, cudaFuncAttributeMaxDynamicSharedMemorySize, smem_gemm);
    cudaFuncSetAttribute(gemm_mma_kernel<6>, cudaFuncAttributeMaxDynamicSharedMemorySize, smem_gemm);

    int nb_n = (n + 255) / 256;
    int nb_e4 = (e + 1023) / 1024;     // 4 edges per thread
    int nb_w = (n + 7) / 8;            // warp-per-node, 256 threads = 8 warps
    int nb_g = (n + 127) / 128;        // gemm row tiles
    int nb_s = (n + 1023) / 1024;      // scan blocks

    // graph prep
    zero_deg_kernel<<<nb_n, 256>>>(n);
    hist_kernel<<<nb_e4, 256>>>(dst, e);
    blockscan_kernel<<<nb_s, 256>>>(n);    // also emits dinv
    addoff_kernel<<<nb_s, 256>>>(n, e);    // tree-reduce bsum prefix + offset add
    scatter_kernel<<<nb_e4, 256>>>(src, dst, e);

    // layer 1: h0 = x @ W1 (fp32 in, split in-kernel), fp16 out; 2 segs in-kernel
    gemm_mma_kernel<2><<<nb_g, 256, smem_gemm>>>(
        x, nullptr, W1, nullptr, 1, 1, H, nullptr, n,
        nullptr, nullptr, nullptr, (__half*)p_h0f);
    // h = relu(Agg(h0) + b1), fp16 out
    gather_kernel<<<nb_w, 256>>>((const __half*)p_h0f, (__half*)p_hf,
                                 nullptr, nullptr, b1, n, 0);

    // fold layer-2 + head weights (bf16 split)
    wprep_kernel<<<dim3(H, 3), H>>>(W2, W2u, Wpca, Wbce, b2, b2u, bpca, bbce);

    // layer 2: agg = Agg(h) (bf16 split out) ; fused GEMM, 6 segs in-kernel
    gather_kernel<<<nb_w, 256>>>((const __half*)p_hf, nullptr,
                                 (__nv_bfloat16*)p_aggh, (__nv_bfloat16*)p_aggl,
                                 nullptr, n, 1);
    gemm_mma_kernel<6><<<nb_g, 256, smem_gemm>>>(
        (const void*)p_aggh, (const void*)p_aggl, (const void*)p_Wbh, (const void*)p_Wbl,
        0, 0, 384, (const float*)p_bbig, n, flab, opca, obce, nullptr);

    // out1 head from feat_label
    out1_kernel<<<nb_w, 256>>>(flab, Wh1, bh1, out1, n);
}